// round 15
// baseline (speedup 1.0000x reference)
#include <cuda_runtime.h>
#include <cuda_bf16.h>
#include <math.h>

// FPQuantizer (fp8_e4m3 flex-bias fake-quant), 8192x8192 fp32. Pure streaming.
//
// Identity: clip(x, -rowabsmax, rowabsmax) == x, so the reference's per-row
// reduction is dead code and the op is purely elementwise:
//
//   bias  = bf16(2^4 - log2(448) + log2(2 - 2^-4) - 1) = 7.15625 = 7 + 0.15625
//   ls    = floor(log2|x| + bias) = (e-127) + 7 + [m >= 2^0.84375]
//   ls    = max(ls, 1)
//   scale = C * 2^(ls - 12),  C = 2^-0.15625
//   out   = rint(x / scale) * scale
//
// Math pipeline (bit-identical to the R13/R14-passing kernels):
//  (a) carry trick: [m >= Cth] folded into the exponent read. With
//      D = 0x800000 - mant(Cth), (|x|_bits + D) >> 23 carries iff m >= Cth;
//      lsBias folded pre-shift (signed >>23).
//  (b) exact-scale fusion: qscale = invC*2^(12-ls) and sc = C*2^(ls-12) built
//      by exponent-field adds on the constants' bit patterns (exact).
//  Per element: LOP.AND, IADD, SHR, IMAX, SHL, ISUB, FMUL, FRND, IADD, FMUL.
//
// R15 change: persistent grid-stride kernel (one occupancy-wave, <=1184
// blocks) replaces the 16384-block one-shot grid — removes ~13 CLC
// wave-transitions + tail-wave drain. Memory pattern per iteration is
// unchanged: 4 front-batched LDG.128 (streaming), 4 STG.128 (streaming).
//
// Zero/subnormal x: e==0 -> (ua + D2) negative -> arithmetic shift -> ls
// clamps to 1; rint(~0 * finite) = 0. Branchless.

__device__ __forceinline__ float fpq_one(float x, unsigned A, unsigned B, int D2) {
    unsigned ua = __float_as_uint(x) & 0x7FFFFFFFu;
    int ls = ((int)(ua + (unsigned)D2)) >> 23;   // floor(log2|x| + bias), carry-folded
    ls = max(ls, 1);
    int ls23 = ls << 23;
    float qscale = __uint_as_float(A - (unsigned)ls23);  // invC * 2^(12-ls), exact
    float q = rintf(x * qscale);                         // one rounding, half-to-even
    float sc = __uint_as_float(B + (unsigned)ls23);      // C * 2^(ls-12), exact
    return q * sc;
}

__device__ __forceinline__ float4 fpq_vec4(float4 v, unsigned A, unsigned B, int D2) {
    float4 r;
    r.x = fpq_one(v.x, A, B, D2);
    r.y = fpq_one(v.y, A, B, D2);
    r.z = fpq_one(v.z, A, B, D2);
    r.w = fpq_one(v.w, A, B, D2);
    return r;
}

// Persistent grid-stride: each iteration does 4 front-batched float4 loads
// (MLP=4) at stride spacing (coalesced across the grid), then 4 stores.
__global__ void __launch_bounds__(256)
FPQuantizer_76312978915927_kernel(const float4* __restrict__ in,
                                  float4* __restrict__ out,
                                  int n4, unsigned A, unsigned B, int D2) {
    int stride = gridDim.x * blockDim.x;
    int i = blockIdx.x * blockDim.x + threadIdx.x;
    // Main loop: 4 float4 per iteration, all in-bounds.
    for (; i + 3 * stride < n4; i += 4 * stride) {
        float4 v0 = __ldcs(&in[i]);
        float4 v1 = __ldcs(&in[i + stride]);
        float4 v2 = __ldcs(&in[i + 2 * stride]);
        float4 v3 = __ldcs(&in[i + 3 * stride]);
        __stcs(&out[i],              fpq_vec4(v0, A, B, D2));
        __stcs(&out[i + stride],     fpq_vec4(v1, A, B, D2));
        __stcs(&out[i + 2 * stride], fpq_vec4(v2, A, B, D2));
        __stcs(&out[i + 3 * stride], fpq_vec4(v3, A, B, D2));
    }
    // Remainder: <=3 strided float4 per thread.
    for (; i < n4; i += stride) {
        __stcs(&out[i], fpq_vec4(__ldcs(&in[i]), A, B, D2));
    }
}

// Scalar tail (n not divisible by 4 -- defensive; 8192*8192 is divisible).
__global__ void FPQuantizer_tail_kernel(const float* __restrict__ in,
                                        float* __restrict__ out,
                                        int start, int n,
                                        unsigned A, unsigned B, int D2) {
    int i = start + blockIdx.x * blockDim.x + threadIdx.x;
    if (i < n) out[i] = fpq_one(in[i], A, B, D2);
}

extern "C" void kernel_launch(void* const* d_in, const int* in_sizes, int n_in,
                              void* d_out, int out_size) {
    const float* x = (const float*)d_in[0];
    float* out = (float*)d_out;
    int n = in_sizes[0];

    // Host-side exact constant derivation (mirrors the reference formula,
    // including the bf16 cast of the bias).
    const double ebits = 4.0, mbits = 5.0, max_norm = 448.0;
    double biasd = pow(2.0, ebits) - log2(max_norm)
                 + log2(2.0 - pow(2.0, 1.0 - mbits)) - 1.0;          // 7.146841...
    float biasbf = __bfloat162float(__float2bfloat16((float)biasd)); // 7.15625
    int ibias = (int)floorf(biasbf);                                  // 7
    double frac = (double)biasbf - (double)ibias;                     // 0.15625
    float C    = (float)pow(2.0, -frac);        // 2^-0.15625 ~= 0.8971
    float invC = (float)(1.0 / (double)C);      // closest float to 1/C_f
    float Cth  = (float)pow(2.0, 1.0 - frac);   // 2^0.84375 ~= 1.794838
    int   lsBias = ibias - 127;                 // -120
    int   sh     = (int)mbits + ibias;          // 12

    // Carry-trick constant: (ua + D2) >> 23 == e + lsBias + [mant >= mant(Cth)]
    unsigned th_bits;  memcpy(&th_bits, &Cth, 4);
    unsigned th_mant = th_bits & 0x007FFFFFu;
    int D2 = (int)(0x00800000u - th_mant) + (lsBias << 23);

    // Exact-scale fused constants:
    //   A - (ls<<23) = bits of invC * 2^(sh - ls)
    //   B + (ls<<23) = bits of C    * 2^(ls - sh)
    unsigned invC_bits; memcpy(&invC_bits, &invC, 4);
    unsigned C_bits;    memcpy(&C_bits,    &C,    4);
    unsigned A = invC_bits + ((unsigned)sh << 23);
    unsigned B = C_bits    - ((unsigned)sh << 23);

    int n4 = n >> 2;
    if (n4 > 0) {
        const int threads = 256;
        const int blocks_per_sm = 8;  // 256 thr x 32 regs -> 8 blocks/SM (full RF)
        int sms = 0;
        if (cudaDeviceGetAttribute(&sms, cudaDevAttrMultiProcessorCount, 0)
                != cudaSuccess || sms <= 0) {
            sms = 148;  // safe fallback (B300 die; GB300 has 152)
        }
        // Exactly one occupancy-wave. Never overshoot (a partial 9th block
        // per SM would serialize a straggler wave); undershooting the block
        // demand is impossible here since n4 >> grid.
        int blocks = sms * blocks_per_sm;
        long long need = ((long long)n4 + threads - 1) / threads;
        if ((long long)blocks > need) blocks = (int)need;
        FPQuantizer_76312978915927_kernel<<<blocks, threads>>>(
            (const float4*)x, (float4*)out, n4, A, B, D2);
    }
    int tail_start = n4 << 2;
    int tail = n - tail_start;
    if (tail > 0) {
        FPQuantizer_tail_kernel<<<1, 128>>>(x, out, tail_start, n, A, B, D2);
    }
}

// round 16
// speedup vs baseline: 1.1356x; 1.1356x over previous
#include <cuda_runtime.h>
#include <cuda_bf16.h>
#include <math.h>

// FPQuantizer (fp8_e4m3 flex-bias fake-quant), 8192x8192 fp32. Pure streaming.
//
// Identity: clip(x, -rowabsmax, rowabsmax) == x, so the reference's per-row
// reduction is dead code and the op is purely elementwise:
//
//   bias  = bf16(2^4 - log2(448) + log2(2 - 2^-4) - 1) = 7.15625 = 7 + 0.15625
//   ls    = floor(log2|x| + bias) = (e-127) + 7 + [m >= 2^0.84375]
//   ls    = max(ls, 1)
//   scale = C * 2^(ls - 12),  C = 2^-0.15625
//   out   = rint(x / scale) * scale
//
// Math pipeline (bit-identical to R13/R14-passing kernels):
//  (a) carry trick: [m >= Cth] folded into the exponent read. With
//      D = 0x800000 - mant(Cth), (|x|_bits + D) >> 23 carries iff m >= Cth;
//      lsBias folded pre-shift (signed >>23).
//  (b) exact-scale fusion: qscale = invC*2^(12-ls) and sc = C*2^(ls-12) built
//      by exponent-field adds on the constants' bit patterns (exact).
//  Per element: LOP.AND, IADD, SHR, IMAX, SHL, ISUB, FMUL, FRND, IADD, FMUL.
//
// R16: revert R15's persistent grid (regressed: loop-carried issue ordering +
// 4.75MB inter-load stride broke MLP and DRAM locality; 81.1us vs 74.3us).
// One-shot 4x-float4 blocks, and for the exact-division case (n4 % 1024 == 0,
// true for 8192^2) an UNGUARDED kernel: no ISETP/predicates, 4 LDG.128
// front-batched unconditionally.
//
// Zero/subnormal x: e==0 -> (ua + D2) negative -> arithmetic shift -> ls
// clamps to 1; rint(~0 * finite) = 0. Branchless.

__device__ __forceinline__ float fpq_one(float x, unsigned A, unsigned B, int D2) {
    unsigned ua = __float_as_uint(x) & 0x7FFFFFFFu;
    int ls = ((int)(ua + (unsigned)D2)) >> 23;   // floor(log2|x| + bias), carry-folded
    ls = max(ls, 1);
    int ls23 = ls << 23;
    float qscale = __uint_as_float(A - (unsigned)ls23);  // invC * 2^(12-ls), exact
    float q = rintf(x * qscale);                         // one rounding, half-to-even
    float sc = __uint_as_float(B + (unsigned)ls23);      // C * 2^(ls-12), exact
    return q * sc;
}

__device__ __forceinline__ float4 fpq_vec4(float4 v, unsigned A, unsigned B, int D2) {
    float4 r;
    r.x = fpq_one(v.x, A, B, D2);
    r.y = fpq_one(v.y, A, B, D2);
    r.z = fpq_one(v.z, A, B, D2);
    r.w = fpq_one(v.w, A, B, D2);
    return r;
}

// Exact-division fast path: every block processes a full 4*blockDim tile.
// No bounds checks at all.
__global__ void __launch_bounds__(256)
FPQuantizer_76312978915927_kernel(const float4* __restrict__ in,
                                  float4* __restrict__ out,
                                  unsigned A, unsigned B, int D2) {
    int base = blockIdx.x * (blockDim.x * 4) + threadIdx.x;
    int i0 = base;
    int i1 = base + blockDim.x;
    int i2 = base + blockDim.x * 2;
    int i3 = base + blockDim.x * 3;
    float4 v0 = __ldcs(&in[i0]);
    float4 v1 = __ldcs(&in[i1]);
    float4 v2 = __ldcs(&in[i2]);
    float4 v3 = __ldcs(&in[i3]);
    __stcs(&out[i0], fpq_vec4(v0, A, B, D2));
    __stcs(&out[i1], fpq_vec4(v1, A, B, D2));
    __stcs(&out[i2], fpq_vec4(v2, A, B, D2));
    __stcs(&out[i3], fpq_vec4(v3, A, B, D2));
}

// Guarded fallback for n4 not divisible by the tile (defensive).
__global__ void __launch_bounds__(256)
FPQuantizer_guarded_kernel(const float4* __restrict__ in,
                           float4* __restrict__ out,
                           int n4, unsigned A, unsigned B, int D2) {
    int base = blockIdx.x * (blockDim.x * 4) + threadIdx.x;
    int i0 = base;
    int i1 = base + blockDim.x;
    int i2 = base + blockDim.x * 2;
    int i3 = base + blockDim.x * 3;
    bool p0 = i0 < n4, p1 = i1 < n4, p2 = i2 < n4, p3 = i3 < n4;
    float4 v0, v1, v2, v3;
    if (p0) v0 = __ldcs(&in[i0]);
    if (p1) v1 = __ldcs(&in[i1]);
    if (p2) v2 = __ldcs(&in[i2]);
    if (p3) v3 = __ldcs(&in[i3]);
    if (p0) __stcs(&out[i0], fpq_vec4(v0, A, B, D2));
    if (p1) __stcs(&out[i1], fpq_vec4(v1, A, B, D2));
    if (p2) __stcs(&out[i2], fpq_vec4(v2, A, B, D2));
    if (p3) __stcs(&out[i3], fpq_vec4(v3, A, B, D2));
}

// Scalar tail (n not divisible by 4 -- defensive; 8192*8192 is divisible).
__global__ void FPQuantizer_tail_kernel(const float* __restrict__ in,
                                        float* __restrict__ out,
                                        int start, int n,
                                        unsigned A, unsigned B, int D2) {
    int i = start + blockIdx.x * blockDim.x + threadIdx.x;
    if (i < n) out[i] = fpq_one(in[i], A, B, D2);
}

extern "C" void kernel_launch(void* const* d_in, const int* in_sizes, int n_in,
                              void* d_out, int out_size) {
    const float* x = (const float*)d_in[0];
    float* out = (float*)d_out;
    int n = in_sizes[0];

    // Host-side exact constant derivation (mirrors the reference formula,
    // including the bf16 cast of the bias).
    const double ebits = 4.0, mbits = 5.0, max_norm = 448.0;
    double biasd = pow(2.0, ebits) - log2(max_norm)
                 + log2(2.0 - pow(2.0, 1.0 - mbits)) - 1.0;          // 7.146841...
    float biasbf = __bfloat162float(__float2bfloat16((float)biasd)); // 7.15625
    int ibias = (int)floorf(biasbf);                                  // 7
    double frac = (double)biasbf - (double)ibias;                     // 0.15625
    float C    = (float)pow(2.0, -frac);        // 2^-0.15625 ~= 0.8971
    float invC = (float)(1.0 / (double)C);      // closest float to 1/C_f
    float Cth  = (float)pow(2.0, 1.0 - frac);   // 2^0.84375 ~= 1.794838
    int   lsBias = ibias - 127;                 // -120
    int   sh     = (int)mbits + ibias;          // 12

    // Carry-trick constant: (ua + D2) >> 23 == e + lsBias + [mant >= mant(Cth)]
    unsigned th_bits;  memcpy(&th_bits, &Cth, 4);
    unsigned th_mant = th_bits & 0x007FFFFFu;
    int D2 = (int)(0x00800000u - th_mant) + (lsBias << 23);

    // Exact-scale fused constants:
    //   A - (ls<<23) = bits of invC * 2^(sh - ls)
    //   B + (ls<<23) = bits of C    * 2^(ls - sh)
    unsigned invC_bits; memcpy(&invC_bits, &invC, 4);
    unsigned C_bits;    memcpy(&C_bits,    &C,    4);
    unsigned A = invC_bits + ((unsigned)sh << 23);
    unsigned B = C_bits    - ((unsigned)sh << 23);

    int n4 = n >> 2;
    const int threads = 256;
    const int per_block = threads * 4;  // 4 float4 per thread
    if (n4 > 0) {
        if (n4 % per_block == 0) {
            // Exact case (8192x8192 -> n4 = 16M = 16384 * 1024): no guards.
            FPQuantizer_76312978915927_kernel<<<n4 / per_block, threads>>>(
                (const float4*)x, (float4*)out, A, B, D2);
        } else {
            int blocks = (n4 + per_block - 1) / per_block;
            FPQuantizer_guarded_kernel<<<blocks, threads>>>(
                (const float4*)x, (float4*)out, n4, A, B, D2);
        }
    }
    int tail_start = n4 << 2;
    int tail = n - tail_start;
    if (tail > 0) {
        FPQuantizer_tail_kernel<<<1, 128>>>(x, out, tail_start, n, A, B, D2);
    }
}